// round 3
// baseline (speedup 1.0000x reference)
#include <cuda_runtime.h>
#include <cuda_bf16.h>
#include <float.h>
#include <math.h>

#define LANE_WEIGHT 1.0f
#define INV_TEMP    10.0f   // 1 / 0.1

// scratch (allocation-free rule: __device__ globals)
__device__ float g_ce_lane[65536];      // ce_per_lane, NL <= 65536
__device__ float g_sample_loss[8192];   // per-sample loss, B <= 8192

// ---------------------------------------------------------------------------
// Shared epilogue: fused softmax CE over cnt (<=64) entries in s_score/s_ts.
//   ce = tmax + log(sum exp(ts - tmax)) - (sum p*ts) / (sum p)
// with p = exp((score - smax) * INV_TEMP).  Writes g_ce_lane[lane].
// ---------------------------------------------------------------------------
__device__ __forceinline__
void lane_ce_epilogue(int lane, int cnt, int tid,
                      const float* s_score, const float* s_ts,
                      float* ra, float* rb, float* rc)
{
    // ---- pass A: maxes ----
    if (tid < 64) {
        ra[tid] = (tid < cnt) ? s_score[tid] : -FLT_MAX;
        rb[tid] = (tid < cnt) ? s_ts[tid]    : -FLT_MAX;
    }
    __syncthreads();
    if (tid < 32) {
        float a = fmaxf(ra[tid], ra[tid + 32]);
        float b = fmaxf(rb[tid], rb[tid + 32]);
        #pragma unroll
        for (int o = 16; o; o >>= 1) {
            a = fmaxf(a, __shfl_xor_sync(0xffffffffu, a, o));
            b = fmaxf(b, __shfl_xor_sync(0xffffffffu, b, o));
        }
        if (tid == 0) { ra[0] = a; rb[0] = b; }
    }
    __syncthreads();
    const float smax = ra[0];
    const float tmax = rb[0];
    __syncthreads();

    // ---- pass B: three sums ----
    float p = 0.0f, ets = 0.0f, pts = 0.0f;
    if (tid < cnt) {
        float ts = s_ts[tid];
        p   = expf((s_score[tid] - smax) * INV_TEMP);
        ets = expf(ts - tmax);
        pts = p * ts;
    }
    if (tid < 64) { ra[tid] = p; rb[tid] = ets; rc[tid] = pts; }
    __syncthreads();
    if (tid < 32) {
        float a = ra[tid] + ra[tid + 32];
        float b = rb[tid] + rb[tid + 32];
        float c = rc[tid] + rc[tid + 32];
        #pragma unroll
        for (int o = 16; o; o >>= 1) {
            a += __shfl_xor_sync(0xffffffffu, a, o);
            b += __shfl_xor_sync(0xffffffffu, b, o);
            c += __shfl_xor_sync(0xffffffffu, c, o);
        }
        if (tid == 0)
            g_ce_lane[lane] = tmax + logf(b) - c / a;
    }
}

__device__ __forceinline__
int find_sample(const int* __restrict__ cls_se, int B, int lane)
{
    int lo = 0, hi = B - 1;
    while (lo < hi) {
        int mid = (lo + hi + 1) >> 1;
        if (cls_se[2 * mid] <= lane) lo = mid; else hi = mid - 1;
    }
    return lo;
}

// ---------------------------------------------------------------------------
// Fast kernel for T == 50: one block per lane.  Phase 1 front-batches all 7
// float4 loads into registers (MLP=7), THEN computes + stores to smem.
// ---------------------------------------------------------------------------
__global__ __launch_bounds__(256, 4)
void traj_ce_T50_kernel(const float* __restrict__ traj_scores,   // [NT]
                        const float* __restrict__ cand,          // [NT, 50, 2]
                        const float* __restrict__ gt,            // [B, 50, 2]
                        const float* __restrict__ scales,        // [B]
                        const int*   __restrict__ cls_se,        // [B, 2]
                        const int*   __restrict__ trj_se,        // [NL, 2]
                        int B)
{
    const int lane = blockIdx.x;
    const int tid  = threadIdx.x;

    const int ts_start = trj_se[2 * lane];
    const int ts_end   = trj_se[2 * lane + 1];
    int cnt = ts_end - ts_start;
    if (cnt > 64) cnt = 64;

    const int sample = find_sample(cls_se, B, lane);

    __shared__ __align__(8) float2 s_gt[50];
    __shared__ float s_sum[1600];             // one partial per float4 (2 points)
    __shared__ float s_score[64], s_ts[64];
    __shared__ float ra[64], rb[64], rc[64];

    if (tid < 50)
        s_gt[tid] = reinterpret_cast<const float2*>(gt)[sample * 50 + tid];
    const float inv_scale = 1.0f / scales[sample];
    __syncthreads();

    // ---- Phase 1a: front-batched coalesced loads (7 independent LDG.128) ----
    const int n4 = cnt * 25;                  // total float4 in this lane region
    const float4* src = reinterpret_cast<const float4*>(cand)
                        + (size_t)ts_start * 25;
    float4 v[7];
    #pragma unroll
    for (int k = 0; k < 7; k++) {
        const int f = tid + 256 * k;
        if (f < n4) v[k] = src[f];
    }

    // ---- Phase 1b: compute + STS.  r_k = (tid + 256k) mod 25, incremental ----
    int r = tid % 25;                         // r for k=0; step +6 mod 25
    #pragma unroll
    for (int k = 0; k < 7; k++) {
        const int f = tid + 256 * k;
        if (f < n4) {
            const int t0 = 2 * r;
            float2 g0 = s_gt[t0];
            float2 g1 = s_gt[t0 + 1];
            float dx0 = v[k].x - g0.x, dy0 = v[k].y - g0.y;
            float dx1 = v[k].z - g1.x, dy1 = v[k].w - g1.y;
            s_sum[f] = sqrtf(fmaf(dx0, dx0, fmaf(dy0, dy0, 1e-12f)))
                     + sqrtf(fmaf(dx1, dx1, fmaf(dy1, dy1, 1e-12f)));
        }
        r += 6; if (r >= 25) r -= 25;         // (r + 256) mod 25
    }
    __syncthreads();

    // ---- Phase 2: per-trajectory sum (stride 25 vs 32 banks: conflict-free) ----
    if (tid < cnt) {
        float s = 0.0f;
        #pragma unroll
        for (int i = 0; i < 25; i++) s += s_sum[25 * tid + i];
        float ade = s * 0.02f;                // / 50
        s_score[tid] = -ade * inv_scale;
        s_ts[tid]    = traj_scores[ts_start + tid];
    }
    __syncthreads();

    lane_ce_epilogue(lane, cnt, tid, s_score, s_ts, ra, rb, rc);
}

// ---------------------------------------------------------------------------
// Generic fallback (any T): 4 threads per trajectory, float2 loads.
// ---------------------------------------------------------------------------
__global__ __launch_bounds__(256)
void traj_ce_kernel(const float* __restrict__ traj_scores,
                    const float* __restrict__ cand,
                    const float* __restrict__ gt,
                    const float* __restrict__ scales,
                    const int*   __restrict__ cls_se,
                    const int*   __restrict__ trj_se,
                    int B, int T)
{
    const int lane = blockIdx.x;
    const int tid  = threadIdx.x;

    const int ts_start = trj_se[2 * lane];
    const int ts_end   = trj_se[2 * lane + 1];
    int cnt = ts_end - ts_start;
    if (cnt > 64) cnt = 64;

    const int sample = find_sample(cls_se, B, lane);

    __shared__ __align__(8) float s_gt[1024];
    __shared__ float s_score[64], s_ts[64];
    __shared__ float ra[64], rb[64], rc[64];

    const int t2 = T * 2;
    for (int i = tid; i < t2 && i < 1024; i += blockDim.x)
        s_gt[i] = gt[(size_t)sample * t2 + i];
    __syncthreads();

    const float inv_scale = 1.0f / scales[sample];

    const int q   = tid >> 2;
    const int sub = tid & 3;
    float acc = 0.0f;
    if (q < cnt) {
        const float2* base = reinterpret_cast<const float2*>(cand)
                             + (size_t)(ts_start + q) * T;
        const float2* g2 = reinterpret_cast<const float2*>(s_gt);
        #pragma unroll 4
        for (int t = sub; t < T; t += 4) {
            float2 c = base[t];
            float2 g = g2[t];
            float dx = c.x - g.x;
            float dy = c.y - g.y;
            acc += sqrtf(fmaf(dx, dx, fmaf(dy, dy, 1e-12f)));
        }
    }
    acc += __shfl_xor_sync(0xffffffffu, acc, 1);
    acc += __shfl_xor_sync(0xffffffffu, acc, 2);

    if (sub == 0 && q < cnt) {
        float ade = acc / (float)T;
        s_score[q] = -ade * inv_scale;
        s_ts[q]    = traj_scores[ts_start + q];
    }
    __syncthreads();

    lane_ce_epilogue(lane, cnt, tid, s_score, s_ts, ra, rb, rc);
}

// ---------------------------------------------------------------------------
// Kernel 2: one warp per sample. Lane-level CE + oracle-weighted traj loss.
// ---------------------------------------------------------------------------
__global__ __launch_bounds__(32)
void sample_loss_kernel(const float* __restrict__ lane_scores,  // [NL]
                        const int*   __restrict__ oracle,       // [NL] (nonzero = true)
                        const int*   __restrict__ cls_se)       // [B, 2]
{
    const int b = blockIdx.x;
    const int i = threadIdx.x;
    const int s = cls_se[2 * b];
    const int e = cls_se[2 * b + 1];
    int cnt = e - s;
    if (cnt > 32) cnt = 32;   // L=16 in this problem

    const bool act = (i < cnt);
    float ls  = act ? lane_scores[s + i] : -FLT_MAX;
    bool  orc = act && (oracle[s + i] != 0);
    float ce  = orc ? g_ce_lane[s + i] : 0.0f;

    float m = ls;
    #pragma unroll
    for (int o = 16; o; o >>= 1) m = fmaxf(m, __shfl_xor_sync(0xffffffffu, m, o));

    float ev = act ? expf(ls - m) : 0.0f;
    float oc = orc ? 1.0f : 0.0f;

    float Z = ev, OC = oc, CE = ce;
    #pragma unroll
    for (int o = 16; o; o >>= 1) {
        Z  += __shfl_xor_sync(0xffffffffu, Z, o);
        OC += __shfl_xor_sync(0xffffffffu, OC, o);
        CE += __shfl_xor_sync(0xffffffffu, CE, o);
    }
    const float lse = logf(Z);
    float llc = orc ? (m + lse - ls) : 0.0f;   // -target*logp numerator
    float LL = llc;
    #pragma unroll
    for (int o = 16; o; o >>= 1) LL += __shfl_xor_sync(0xffffffffu, LL, o);

    if (i == 0) {
        float lane_loss = (LL / OC) * LANE_WEIGHT;
        float traj_loss = CE / OC;
        g_sample_loss[b] = lane_loss + traj_loss;
    }
}

// ---------------------------------------------------------------------------
// Kernel 3: mean over B samples -> d_out[0]
// ---------------------------------------------------------------------------
__global__ __launch_bounds__(256)
void final_mean_kernel(float* __restrict__ out, int B)
{
    __shared__ float red[256];
    const int tid = threadIdx.x;
    float v = 0.0f;
    for (int i = tid; i < B; i += 256) v += g_sample_loss[i];
    red[tid] = v;
    __syncthreads();
    for (int o = 128; o >= 32; o >>= 1) {
        if (tid < o) red[tid] += red[tid + o];
        __syncthreads();
    }
    if (tid < 32) {
        float a = red[tid];
        #pragma unroll
        for (int o = 16; o; o >>= 1) a += __shfl_xor_sync(0xffffffffu, a, o);
        if (tid == 0) out[0] = a / (float)B;
    }
}

// ---------------------------------------------------------------------------
extern "C" void kernel_launch(void* const* d_in, const int* in_sizes, int n_in,
                              void* d_out, int out_size)
{
    const float* lane_scores = (const float*)d_in[0];   // [NL]
    const float* traj_scores = (const float*)d_in[1];   // [NT, 1]
    const float* cand        = (const float*)d_in[2];   // [NT, T, 2]
    const float* gt          = (const float*)d_in[3];   // [B, T, 2]
    const float* scales      = (const float*)d_in[4];   // [B]
    const int*   oracle      = (const int*)  d_in[5];   // [NL]
    const int*   cls_se      = (const int*)  d_in[6];   // [B, 2]
    const int*   trj_se      = (const int*)  d_in[7];   // [NL, 2]

    const int NL = in_sizes[0];
    const int B  = in_sizes[6] / 2;
    const int T  = in_sizes[3] / (2 * B);

    if (T == 50) {
        traj_ce_T50_kernel<<<NL, 256>>>(traj_scores, cand, gt, scales,
                                        cls_se, trj_se, B);
    } else {
        traj_ce_kernel<<<NL, 256>>>(traj_scores, cand, gt, scales,
                                    cls_se, trj_se, B, T);
    }
    sample_loss_kernel<<<B, 32>>>(lane_scores, oracle, cls_se);
    final_mean_kernel<<<1, 256>>>((float*)d_out, B);
}

// round 4
// speedup vs baseline: 1.0640x; 1.0640x over previous
#include <cuda_runtime.h>
#include <cuda_bf16.h>
#include <float.h>
#include <math.h>

#define LANE_WEIGHT 1.0f
#define INV_TEMP    10.0f   // 1 / 0.1

// scratch (allocation-free rule: __device__ globals)
__device__ float g_ce_lane[65536];      // ce_per_lane, NL <= 65536
__device__ float g_sample_loss[8192];   // per-sample loss, B <= 8192

__device__ __forceinline__ float fsqrt_approx(float x) {
    float r;
    asm("sqrt.approx.f32 %0, %1;" : "=f"(r) : "f"(x));
    return r;
}

__device__ __forceinline__
int find_sample(const int* __restrict__ cls_se, int B, int lane)
{
    int lo = 0, hi = B - 1;
    while (lo < hi) {
        int mid = (lo + hi + 1) >> 1;
        if (cls_se[2 * mid] <= lane) lo = mid; else hi = mid - 1;
    }
    return lo;
}

// ---------------------------------------------------------------------------
// Fast kernel for T == 50: one block per lane.
//   Phase 1a: 7 front-batched LDG.128 per thread (issued FIRST, before index
//             math, so DRAM latency overlaps the binary search + gt load).
//   Phase 1b: approx-sqrt distances -> smem partials (one float per float4).
//   Phase 2 + epilogue: warp 0 only, thread i owns trajs i and i+32; all
//             reductions are warp shuffles.  Only 2 block barriers total.
// ---------------------------------------------------------------------------
__global__ __launch_bounds__(256, 4)
void traj_ce_T50_kernel(const float* __restrict__ traj_scores,   // [NT]
                        const float* __restrict__ cand,          // [NT, 50, 2]
                        const float* __restrict__ gt,            // [B, 50, 2]
                        const float* __restrict__ scales,        // [B]
                        const int*   __restrict__ cls_se,        // [B, 2]
                        const int*   __restrict__ trj_se,        // [NL, 2]
                        int B)
{
    const int lane = blockIdx.x;
    const int tid  = threadIdx.x;

    const int ts_start = trj_se[2 * lane];
    const int ts_end   = trj_se[2 * lane + 1];
    int cnt = ts_end - ts_start;
    if (cnt > 64) cnt = 64;

    __shared__ __align__(8) float2 s_gt[50];
    __shared__ float s_sum[1600];

    // ---- Phase 1a: front-batched coalesced loads (7 independent LDG.128) ----
    const int n4 = cnt * 25;
    const float4* src = reinterpret_cast<const float4*>(cand)
                        + (size_t)ts_start * 25;
    float4 v[7];
    #pragma unroll
    for (int k = 0; k < 7; k++) {
        const int f = tid + 256 * k;
        if (f < n4) v[k] = src[f];
    }

    // ---- index math + gt staging (overlaps the DRAM latency above) ----
    const int sample = find_sample(cls_se, B, lane);
    if (tid < 50)
        s_gt[tid] = reinterpret_cast<const float2*>(gt)[sample * 50 + tid];
    const float inv_scale = 1.0f / scales[sample];
    __syncthreads();

    // ---- Phase 1b: compute + STS.  r_k = (tid + 256k) mod 25, incremental ----
    int r = tid % 25;
    #pragma unroll
    for (int k = 0; k < 7; k++) {
        const int f = tid + 256 * k;
        if (f < n4) {
            const int t0 = 2 * r;
            float2 g0 = s_gt[t0];
            float2 g1 = s_gt[t0 + 1];
            float dx0 = v[k].x - g0.x, dy0 = v[k].y - g0.y;
            float dx1 = v[k].z - g1.x, dy1 = v[k].w - g1.y;
            s_sum[f] = fsqrt_approx(fmaf(dx0, dx0, fmaf(dy0, dy0, 1e-12f)))
                     + fsqrt_approx(fmaf(dx1, dx1, fmaf(dy1, dy1, 1e-12f)));
        }
        r += 6; if (r >= 25) r -= 25;         // (r + 256) mod 25
    }
    __syncthreads();

    // ---- Phase 2 + epilogue: warp 0 only ----
    if (tid >= 32) return;

    const bool actA = (tid < cnt);
    const bool actB = (tid + 32 < cnt);

    float sA = -FLT_MAX, sB = -FLT_MAX;     // -ade/scale scores
    float tA = -FLT_MAX, tB = -FLT_MAX;     // traj_scores
    if (actA) {
        float s = 0.0f;
        #pragma unroll
        for (int i = 0; i < 25; i++) s += s_sum[25 * tid + i];
        sA = -(s * 0.02f) * inv_scale;
        tA = traj_scores[ts_start + tid];
    }
    if (actB) {
        float s = 0.0f;
        #pragma unroll
        for (int i = 0; i < 25; i++) s += s_sum[25 * (tid + 32) + i];
        sB = -(s * 0.02f) * inv_scale;
        tB = traj_scores[ts_start + tid + 32];
    }

    // maxes over all cnt entries
    float smax = fmaxf(sA, sB);
    float tmax = fmaxf(tA, tB);
    #pragma unroll
    for (int o = 16; o; o >>= 1) {
        smax = fmaxf(smax, __shfl_xor_sync(0xffffffffu, smax, o));
        tmax = fmaxf(tmax, __shfl_xor_sync(0xffffffffu, tmax, o));
    }

    // three sums: P = sum p, E = sum exp(ts - tmax), PT = sum p*ts
    float pA = actA ? expf((sA - smax) * INV_TEMP) : 0.0f;
    float pB = actB ? expf((sB - smax) * INV_TEMP) : 0.0f;
    float eA = actA ? expf(tA - tmax) : 0.0f;
    float eB = actB ? expf(tB - tmax) : 0.0f;

    float P  = pA + pB;
    float E  = eA + eB;
    float PT = (actA ? pA * tA : 0.0f) + (actB ? pB * tB : 0.0f);
    #pragma unroll
    for (int o = 16; o; o >>= 1) {
        P  += __shfl_xor_sync(0xffffffffu, P,  o);
        E  += __shfl_xor_sync(0xffffffffu, E,  o);
        PT += __shfl_xor_sync(0xffffffffu, PT, o);
    }

    if (tid == 0)
        g_ce_lane[lane] = tmax + logf(E) - PT / P;
}

// ---------------------------------------------------------------------------
// Generic fallback (any T): 4 threads per trajectory, float2 loads.
// ---------------------------------------------------------------------------
__global__ __launch_bounds__(256)
void traj_ce_kernel(const float* __restrict__ traj_scores,
                    const float* __restrict__ cand,
                    const float* __restrict__ gt,
                    const float* __restrict__ scales,
                    const int*   __restrict__ cls_se,
                    const int*   __restrict__ trj_se,
                    int B, int T)
{
    const int lane = blockIdx.x;
    const int tid  = threadIdx.x;

    const int ts_start = trj_se[2 * lane];
    const int ts_end   = trj_se[2 * lane + 1];
    int cnt = ts_end - ts_start;
    if (cnt > 64) cnt = 64;

    const int sample = find_sample(cls_se, B, lane);

    __shared__ __align__(8) float s_gt[1024];
    __shared__ float s_score[64], s_ts[64];

    const int t2 = T * 2;
    for (int i = tid; i < t2 && i < 1024; i += blockDim.x)
        s_gt[i] = gt[(size_t)sample * t2 + i];
    __syncthreads();

    const float inv_scale = 1.0f / scales[sample];

    const int q   = tid >> 2;
    const int sub = tid & 3;
    float acc = 0.0f;
    if (q < cnt) {
        const float2* base = reinterpret_cast<const float2*>(cand)
                             + (size_t)(ts_start + q) * T;
        const float2* g2 = reinterpret_cast<const float2*>(s_gt);
        #pragma unroll 4
        for (int t = sub; t < T; t += 4) {
            float2 c = base[t];
            float2 g = g2[t];
            float dx = c.x - g.x;
            float dy = c.y - g.y;
            acc += fsqrt_approx(fmaf(dx, dx, fmaf(dy, dy, 1e-12f)));
        }
    }
    acc += __shfl_xor_sync(0xffffffffu, acc, 1);
    acc += __shfl_xor_sync(0xffffffffu, acc, 2);

    if (sub == 0 && q < cnt) {
        float ade = acc / (float)T;
        s_score[q] = -ade * inv_scale;
        s_ts[q]    = traj_scores[ts_start + q];
    }
    __syncthreads();

    // epilogue on warp 0, thread i owns entries i and i+32
    if (tid >= 32) return;
    const bool actA = (tid < cnt);
    const bool actB = (tid + 32 < cnt);
    float sA = actA ? s_score[tid]      : -FLT_MAX;
    float sB = actB ? s_score[tid + 32] : -FLT_MAX;
    float tA = actA ? s_ts[tid]         : -FLT_MAX;
    float tB = actB ? s_ts[tid + 32]    : -FLT_MAX;

    float smax = fmaxf(sA, sB);
    float tmax = fmaxf(tA, tB);
    #pragma unroll
    for (int o = 16; o; o >>= 1) {
        smax = fmaxf(smax, __shfl_xor_sync(0xffffffffu, smax, o));
        tmax = fmaxf(tmax, __shfl_xor_sync(0xffffffffu, tmax, o));
    }
    float pA = actA ? expf((sA - smax) * INV_TEMP) : 0.0f;
    float pB = actB ? expf((sB - smax) * INV_TEMP) : 0.0f;
    float eA = actA ? expf(tA - tmax) : 0.0f;
    float eB = actB ? expf(tB - tmax) : 0.0f;
    float P  = pA + pB;
    float E  = eA + eB;
    float PT = (actA ? pA * tA : 0.0f) + (actB ? pB * tB : 0.0f);
    #pragma unroll
    for (int o = 16; o; o >>= 1) {
        P  += __shfl_xor_sync(0xffffffffu, P,  o);
        E  += __shfl_xor_sync(0xffffffffu, E,  o);
        PT += __shfl_xor_sync(0xffffffffu, PT, o);
    }
    if (tid == 0)
        g_ce_lane[lane] = tmax + logf(E) - PT / P;
}

// ---------------------------------------------------------------------------
// Kernel 2: one warp per sample. Lane-level CE + oracle-weighted traj loss.
// ---------------------------------------------------------------------------
__global__ __launch_bounds__(32)
void sample_loss_kernel(const float* __restrict__ lane_scores,  // [NL]
                        const int*   __restrict__ oracle,       // [NL] (nonzero = true)
                        const int*   __restrict__ cls_se)       // [B, 2]
{
    const int b = blockIdx.x;
    const int i = threadIdx.x;
    const int s = cls_se[2 * b];
    const int e = cls_se[2 * b + 1];
    int cnt = e - s;
    if (cnt > 32) cnt = 32;   // L=16 in this problem

    const bool act = (i < cnt);
    float ls  = act ? lane_scores[s + i] : -FLT_MAX;
    bool  orc = act && (oracle[s + i] != 0);
    float ce  = orc ? g_ce_lane[s + i] : 0.0f;

    float m = ls;
    #pragma unroll
    for (int o = 16; o; o >>= 1) m = fmaxf(m, __shfl_xor_sync(0xffffffffu, m, o));

    float ev = act ? expf(ls - m) : 0.0f;
    float oc = orc ? 1.0f : 0.0f;

    float Z = ev, OC = oc, CE = ce;
    #pragma unroll
    for (int o = 16; o; o >>= 1) {
        Z  += __shfl_xor_sync(0xffffffffu, Z, o);
        OC += __shfl_xor_sync(0xffffffffu, OC, o);
        CE += __shfl_xor_sync(0xffffffffu, CE, o);
    }
    const float lse = logf(Z);
    float llc = orc ? (m + lse - ls) : 0.0f;   // -target*logp numerator
    float LL = llc;
    #pragma unroll
    for (int o = 16; o; o >>= 1) LL += __shfl_xor_sync(0xffffffffu, LL, o);

    if (i == 0) {
        float lane_loss = (LL / OC) * LANE_WEIGHT;
        float traj_loss = CE / OC;
        g_sample_loss[b] = lane_loss + traj_loss;
    }
}

// ---------------------------------------------------------------------------
// Kernel 3: mean over B samples -> d_out[0]
// ---------------------------------------------------------------------------
__global__ __launch_bounds__(256)
void final_mean_kernel(float* __restrict__ out, int B)
{
    __shared__ float red[256];
    const int tid = threadIdx.x;
    float v = 0.0f;
    for (int i = tid; i < B; i += 256) v += g_sample_loss[i];
    red[tid] = v;
    __syncthreads();
    for (int o = 128; o >= 32; o >>= 1) {
        if (tid < o) red[tid] += red[tid + o];
        __syncthreads();
    }
    if (tid < 32) {
        float a = red[tid];
        #pragma unroll
        for (int o = 16; o; o >>= 1) a += __shfl_xor_sync(0xffffffffu, a, o);
        if (tid == 0) out[0] = a / (float)B;
    }
}

// ---------------------------------------------------------------------------
extern "C" void kernel_launch(void* const* d_in, const int* in_sizes, int n_in,
                              void* d_out, int out_size)
{
    const float* lane_scores = (const float*)d_in[0];   // [NL]
    const float* traj_scores = (const float*)d_in[1];   // [NT, 1]
    const float* cand        = (const float*)d_in[2];   // [NT, T, 2]
    const float* gt          = (const float*)d_in[3];   // [B, T, 2]
    const float* scales      = (const float*)d_in[4];   // [B]
    const int*   oracle      = (const int*)  d_in[5];   // [NL]
    const int*   cls_se      = (const int*)  d_in[6];   // [B, 2]
    const int*   trj_se      = (const int*)  d_in[7];   // [NL, 2]

    const int NL = in_sizes[0];
    const int B  = in_sizes[6] / 2;
    const int T  = in_sizes[3] / (2 * B);

    if (T == 50) {
        traj_ce_T50_kernel<<<NL, 256>>>(traj_scores, cand, gt, scales,
                                        cls_se, trj_se, B);
    } else {
        traj_ce_kernel<<<NL, 256>>>(traj_scores, cand, gt, scales,
                                    cls_se, trj_se, B, T);
    }
    sample_loss_kernel<<<B, 32>>>(lane_scores, oracle, cls_se);
    final_mean_kernel<<<1, 256>>>((float*)d_out, B);
}

// round 5
// speedup vs baseline: 1.3184x; 1.2391x over previous
#include <cuda_runtime.h>
#include <cuda_bf16.h>
#include <float.h>
#include <math.h>

#define LANE_WEIGHT 1.0f
#define INV_TEMP    10.0f   // 1 / 0.1

// scratch (allocation-free rule: __device__ globals)
__device__ float g_score[524288];       // per-trajectory score, NT <= 524288
__device__ float g_ce_lane[65536];      // ce_per_lane, NL <= 65536
__device__ float g_sample_loss[8192];   // per-sample loss, B <= 8192

__device__ __forceinline__ float fsqrt_approx(float x) {
    float r;
    asm("sqrt.approx.f32 %0, %1;" : "=f"(r) : "f"(x));
    return r;
}

__device__ __forceinline__
int find_sample(const int* __restrict__ cls_se, int B, int lane)
{
    int lo = 0, hi = B - 1;
    while (lo < hi) {
        int mid = (lo + hi + 1) >> 1;
        if (cls_se[2 * mid] <= lane) lo = mid; else hi = mid - 1;
    }
    return lo;
}

// ---------------------------------------------------------------------------
// Kernel A (T == 50): pure streaming ADE.  One block per lane, one quad of
// threads per trajectory.  NO __syncthreads, NO shared memory: every warp
// streams independently, keeping DRAM loads in flight for its whole life.
//   quad lane sub handles float4 indices r = sub, sub+4, ..., (<25)
//   gt read via __ldg (tiny, L1/L2 resident, quasi-broadcast within warp)
// ---------------------------------------------------------------------------
__global__ __launch_bounds__(256)
void traj_ade_T50_kernel(const float* __restrict__ cand,   // [NT, 50, 2]
                         const float* __restrict__ gt,     // [B, 50, 2]
                         const float* __restrict__ scales, // [B]
                         const int*   __restrict__ cls_se, // [B, 2]
                         const int*   __restrict__ trj_se, // [NL, 2]
                         int B)
{
    const int lane = blockIdx.x;
    const int tid  = threadIdx.x;

    const int ts_start = trj_se[2 * lane];
    const int ts_end   = trj_se[2 * lane + 1];
    int cnt = ts_end - ts_start;
    if (cnt > 64) cnt = 64;

    const int sample = find_sample(cls_se, B, lane);
    const float inv_scale = 1.0f / scales[sample];

    const int tl  = tid >> 2;          // trajectory within lane (0..63)
    const int sub = tid & 3;

    float acc0 = 0.0f, acc1 = 0.0f;
    if (tl < cnt) {
        const float4* base = reinterpret_cast<const float4*>(cand)
                             + (size_t)(ts_start + tl) * 25;
        const float2* gt2 = reinterpret_cast<const float2*>(gt) + sample * 50;
        #pragma unroll
        for (int j = 0; j < 7; j++) {
            const int r = sub + 4 * j;
            if (r < 25) {
                float4 v  = base[r];
                float2 g0 = __ldg(&gt2[2 * r]);
                float2 g1 = __ldg(&gt2[2 * r + 1]);
                float dx0 = v.x - g0.x, dy0 = v.y - g0.y;
                float dx1 = v.z - g1.x, dy1 = v.w - g1.y;
                acc0 += fsqrt_approx(fmaf(dx0, dx0, fmaf(dy0, dy0, 1e-12f)));
                acc1 += fsqrt_approx(fmaf(dx1, dx1, fmaf(dy1, dy1, 1e-12f)));
            }
        }
    }
    float acc = acc0 + acc1;
    acc += __shfl_xor_sync(0xffffffffu, acc, 1);
    acc += __shfl_xor_sync(0xffffffffu, acc, 2);

    if (sub == 0 && tl < cnt)
        g_score[ts_start + tl] = -(acc * 0.02f) * inv_scale;
}

// ---------------------------------------------------------------------------
// Kernel B: fused softmax CE per lane.  One warp per lane (8 lanes / block).
//   ce = tmax + log(sum exp(ts - tmax)) - (sum p*ts) / (sum p)
//   p  = exp((score - smax) * INV_TEMP)
// ---------------------------------------------------------------------------
__global__ __launch_bounds__(256)
void lane_ce_kernel(const float* __restrict__ traj_scores,   // [NT]
                    const int*   __restrict__ trj_se,        // [NL, 2]
                    int NL)
{
    const int wid  = threadIdx.x >> 5;
    const int lid  = threadIdx.x & 31;
    const int lane = blockIdx.x * 8 + wid;
    if (lane >= NL) return;

    const int ts_start = trj_se[2 * lane];
    const int ts_end   = trj_se[2 * lane + 1];
    int cnt = ts_end - ts_start;
    if (cnt > 64) cnt = 64;

    const bool actA = (lid < cnt);
    const bool actB = (lid + 32 < cnt);

    float sA = actA ? g_score[ts_start + lid]            : -FLT_MAX;
    float sB = actB ? g_score[ts_start + lid + 32]       : -FLT_MAX;
    float tA = actA ? traj_scores[ts_start + lid]        : -FLT_MAX;
    float tB = actB ? traj_scores[ts_start + lid + 32]   : -FLT_MAX;

    float smax = fmaxf(sA, sB);
    float tmax = fmaxf(tA, tB);
    #pragma unroll
    for (int o = 16; o; o >>= 1) {
        smax = fmaxf(smax, __shfl_xor_sync(0xffffffffu, smax, o));
        tmax = fmaxf(tmax, __shfl_xor_sync(0xffffffffu, tmax, o));
    }

    float pA = actA ? expf((sA - smax) * INV_TEMP) : 0.0f;
    float pB = actB ? expf((sB - smax) * INV_TEMP) : 0.0f;
    float eA = actA ? expf(tA - tmax) : 0.0f;
    float eB = actB ? expf(tB - tmax) : 0.0f;

    float P  = pA + pB;
    float E  = eA + eB;
    float PT = (actA ? pA * tA : 0.0f) + (actB ? pB * tB : 0.0f);
    #pragma unroll
    for (int o = 16; o; o >>= 1) {
        P  += __shfl_xor_sync(0xffffffffu, P,  o);
        E  += __shfl_xor_sync(0xffffffffu, E,  o);
        PT += __shfl_xor_sync(0xffffffffu, PT, o);
    }

    if (lid == 0)
        g_ce_lane[lane] = tmax + logf(E) - PT / P;
}

// ---------------------------------------------------------------------------
// Generic fallback (any T): 4 threads per trajectory, float2 loads,
// block-per-lane with in-block epilogue (kept from R4; correct for any T).
// ---------------------------------------------------------------------------
__global__ __launch_bounds__(256)
void traj_ce_kernel(const float* __restrict__ traj_scores,
                    const float* __restrict__ cand,
                    const float* __restrict__ gt,
                    const float* __restrict__ scales,
                    const int*   __restrict__ cls_se,
                    const int*   __restrict__ trj_se,
                    int B, int T)
{
    const int lane = blockIdx.x;
    const int tid  = threadIdx.x;

    const int ts_start = trj_se[2 * lane];
    const int ts_end   = trj_se[2 * lane + 1];
    int cnt = ts_end - ts_start;
    if (cnt > 64) cnt = 64;

    const int sample = find_sample(cls_se, B, lane);

    __shared__ __align__(8) float s_gt[1024];
    __shared__ float s_score[64], s_ts[64];

    const int t2 = T * 2;
    for (int i = tid; i < t2 && i < 1024; i += blockDim.x)
        s_gt[i] = gt[(size_t)sample * t2 + i];
    __syncthreads();

    const float inv_scale = 1.0f / scales[sample];

    const int q   = tid >> 2;
    const int sub = tid & 3;
    float acc = 0.0f;
    if (q < cnt) {
        const float2* base = reinterpret_cast<const float2*>(cand)
                             + (size_t)(ts_start + q) * T;
        const float2* g2 = reinterpret_cast<const float2*>(s_gt);
        #pragma unroll 4
        for (int t = sub; t < T; t += 4) {
            float2 c = base[t];
            float2 g = g2[t];
            float dx = c.x - g.x;
            float dy = c.y - g.y;
            acc += fsqrt_approx(fmaf(dx, dx, fmaf(dy, dy, 1e-12f)));
        }
    }
    acc += __shfl_xor_sync(0xffffffffu, acc, 1);
    acc += __shfl_xor_sync(0xffffffffu, acc, 2);

    if (sub == 0 && q < cnt) {
        float ade = acc / (float)T;
        s_score[q] = -ade * inv_scale;
        s_ts[q]    = traj_scores[ts_start + q];
    }
    __syncthreads();

    if (tid >= 32) return;
    const bool actA = (tid < cnt);
    const bool actB = (tid + 32 < cnt);
    float sA = actA ? s_score[tid]      : -FLT_MAX;
    float sB = actB ? s_score[tid + 32] : -FLT_MAX;
    float tA = actA ? s_ts[tid]         : -FLT_MAX;
    float tB = actB ? s_ts[tid + 32]    : -FLT_MAX;

    float smax = fmaxf(sA, sB);
    float tmax = fmaxf(tA, tB);
    #pragma unroll
    for (int o = 16; o; o >>= 1) {
        smax = fmaxf(smax, __shfl_xor_sync(0xffffffffu, smax, o));
        tmax = fmaxf(tmax, __shfl_xor_sync(0xffffffffu, tmax, o));
    }
    float pA = actA ? expf((sA - smax) * INV_TEMP) : 0.0f;
    float pB = actB ? expf((sB - smax) * INV_TEMP) : 0.0f;
    float eA = actA ? expf(tA - tmax) : 0.0f;
    float eB = actB ? expf(tB - tmax) : 0.0f;
    float P  = pA + pB;
    float E  = eA + eB;
    float PT = (actA ? pA * tA : 0.0f) + (actB ? pB * tB : 0.0f);
    #pragma unroll
    for (int o = 16; o; o >>= 1) {
        P  += __shfl_xor_sync(0xffffffffu, P,  o);
        E  += __shfl_xor_sync(0xffffffffu, E,  o);
        PT += __shfl_xor_sync(0xffffffffu, PT, o);
    }
    if (tid == 0)
        g_ce_lane[lane] = tmax + logf(E) - PT / P;
}

// ---------------------------------------------------------------------------
// Kernel 2: one warp per sample. Lane-level CE + oracle-weighted traj loss.
// ---------------------------------------------------------------------------
__global__ __launch_bounds__(32)
void sample_loss_kernel(const float* __restrict__ lane_scores,  // [NL]
                        const int*   __restrict__ oracle,       // [NL] (nonzero = true)
                        const int*   __restrict__ cls_se)       // [B, 2]
{
    const int b = blockIdx.x;
    const int i = threadIdx.x;
    const int s = cls_se[2 * b];
    const int e = cls_se[2 * b + 1];
    int cnt = e - s;
    if (cnt > 32) cnt = 32;   // L=16 in this problem

    const bool act = (i < cnt);
    float ls  = act ? lane_scores[s + i] : -FLT_MAX;
    bool  orc = act && (oracle[s + i] != 0);
    float ce  = orc ? g_ce_lane[s + i] : 0.0f;

    float m = ls;
    #pragma unroll
    for (int o = 16; o; o >>= 1) m = fmaxf(m, __shfl_xor_sync(0xffffffffu, m, o));

    float ev = act ? expf(ls - m) : 0.0f;
    float oc = orc ? 1.0f : 0.0f;

    float Z = ev, OC = oc, CE = ce;
    #pragma unroll
    for (int o = 16; o; o >>= 1) {
        Z  += __shfl_xor_sync(0xffffffffu, Z, o);
        OC += __shfl_xor_sync(0xffffffffu, OC, o);
        CE += __shfl_xor_sync(0xffffffffu, CE, o);
    }
    const float lse = logf(Z);
    float llc = orc ? (m + lse - ls) : 0.0f;   // -target*logp numerator
    float LL = llc;
    #pragma unroll
    for (int o = 16; o; o >>= 1) LL += __shfl_xor_sync(0xffffffffu, LL, o);

    if (i == 0) {
        float lane_loss = (LL / OC) * LANE_WEIGHT;
        float traj_loss = CE / OC;
        g_sample_loss[b] = lane_loss + traj_loss;
    }
}

// ---------------------------------------------------------------------------
// Kernel 3: mean over B samples -> d_out[0]
// ---------------------------------------------------------------------------
__global__ __launch_bounds__(256)
void final_mean_kernel(float* __restrict__ out, int B)
{
    __shared__ float red[256];
    const int tid = threadIdx.x;
    float v = 0.0f;
    for (int i = tid; i < B; i += 256) v += g_sample_loss[i];
    red[tid] = v;
    __syncthreads();
    for (int o = 128; o >= 32; o >>= 1) {
        if (tid < o) red[tid] += red[tid + o];
        __syncthreads();
    }
    if (tid < 32) {
        float a = red[tid];
        #pragma unroll
        for (int o = 16; o; o >>= 1) a += __shfl_xor_sync(0xffffffffu, a, o);
        if (tid == 0) out[0] = a / (float)B;
    }
}

// ---------------------------------------------------------------------------
extern "C" void kernel_launch(void* const* d_in, const int* in_sizes, int n_in,
                              void* d_out, int out_size)
{
    const float* lane_scores = (const float*)d_in[0];   // [NL]
    const float* traj_scores = (const float*)d_in[1];   // [NT, 1]
    const float* cand        = (const float*)d_in[2];   // [NT, T, 2]
    const float* gt          = (const float*)d_in[3];   // [B, T, 2]
    const float* scales      = (const float*)d_in[4];   // [B]
    const int*   oracle      = (const int*)  d_in[5];   // [NL]
    const int*   cls_se      = (const int*)  d_in[6];   // [B, 2]
    const int*   trj_se      = (const int*)  d_in[7];   // [NL, 2]

    const int NL = in_sizes[0];
    const int NT = in_sizes[1];
    const int B  = in_sizes[6] / 2;
    const int T  = in_sizes[3] / (2 * B);

    if (T == 50 && NT <= 524288) {
        traj_ade_T50_kernel<<<NL, 256>>>(cand, gt, scales, cls_se, trj_se, B);
        lane_ce_kernel<<<(NL + 7) / 8, 256>>>(traj_scores, trj_se, NL);
    } else {
        traj_ce_kernel<<<NL, 256>>>(traj_scores, cand, gt, scales,
                                    cls_se, trj_se, B, T);
    }
    sample_loss_kernel<<<B, 32>>>(lane_scores, oracle, cls_se);
    final_mean_kernel<<<1, 256>>>((float*)d_out, B);
}

// round 9
// speedup vs baseline: 1.3571x; 1.0293x over previous
#include <cuda_runtime.h>
#include <cuda_bf16.h>
#include <float.h>
#include <math.h>

#define LANE_WEIGHT 1.0f
#define INV_TEMP    10.0f   // 1 / 0.1

// scratch (allocation-free rule: __device__ globals)
__device__ float g_score[524288];       // per-trajectory score, NT <= 524288
__device__ float g_ce_lane[65536];      // ce_per_lane (fallback path)
__device__ float g_sample_loss[8192];   // per-sample loss, B <= 8192
__device__ int   g_done = 0;            // last-block ticket (self-resetting)

__device__ __forceinline__ float fsqrt_approx(float x) {
    float r;
    asm("sqrt.approx.f32 %0, %1;" : "=f"(r) : "f"(x));
    return r;
}

__device__ __forceinline__
int find_sample(const int* __restrict__ cls_se, int B, int lane)
{
    int lo = 0, hi = B - 1;
    while (lo < hi) {
        int mid = (lo + hi + 1) >> 1;
        if (cls_se[2 * mid] <= lane) lo = mid; else hi = mid - 1;
    }
    return lo;
}

// ---------------------------------------------------------------------------
// Per-lane fused softmax CE from registers (two entries per thread, warp-wide).
//   ce = tmax + log(sum exp(ts-tmax)) - (sum p*ts)/(sum p),
//   p = exp((score-smax)*INV_TEMP).  Returns value valid on ALL lanes of warp.
// ---------------------------------------------------------------------------
__device__ __forceinline__
float warp_lane_ce(bool actA, bool actB, float sA, float sB, float tA, float tB)
{
    float smax = fmaxf(sA, sB);
    float tmax = fmaxf(tA, tB);
    #pragma unroll
    for (int o = 16; o; o >>= 1) {
        smax = fmaxf(smax, __shfl_xor_sync(0xffffffffu, smax, o));
        tmax = fmaxf(tmax, __shfl_xor_sync(0xffffffffu, tmax, o));
    }
    float pA = actA ? expf((sA - smax) * INV_TEMP) : 0.0f;
    float pB = actB ? expf((sB - smax) * INV_TEMP) : 0.0f;
    float eA = actA ? expf(tA - tmax) : 0.0f;
    float eB = actB ? expf(tB - tmax) : 0.0f;
    float P  = pA + pB;
    float E  = eA + eB;
    float PT = (actA ? pA * tA : 0.0f) + (actB ? pB * tB : 0.0f);
    #pragma unroll
    for (int o = 16; o; o >>= 1) {
        P  += __shfl_xor_sync(0xffffffffu, P,  o);
        E  += __shfl_xor_sync(0xffffffffu, E,  o);
        PT += __shfl_xor_sync(0xffffffffu, PT, o);
    }
    return tmax + logf(E) - PT / P;
}

// ---------------------------------------------------------------------------
// Kernel A (T == 50): pure streaming ADE.  One block per lane, one quad of
// threads per trajectory.  NO __syncthreads, NO shared memory: every warp
// streams independently, keeping DRAM loads in flight for its whole life.
// ---------------------------------------------------------------------------
__global__ __launch_bounds__(256)
void traj_ade_T50_kernel(const float* __restrict__ cand,   // [NT, 50, 2]
                         const float* __restrict__ gt,     // [B, 50, 2]
                         const float* __restrict__ scales, // [B]
                         const int*   __restrict__ cls_se, // [B, 2]
                         const int*   __restrict__ trj_se, // [NL, 2]
                         int B)
{
    const int lane = blockIdx.x;
    const int tid  = threadIdx.x;

    const int ts_start = trj_se[2 * lane];
    const int ts_end   = trj_se[2 * lane + 1];
    int cnt = ts_end - ts_start;
    if (cnt > 64) cnt = 64;

    const int sample = find_sample(cls_se, B, lane);
    const float inv_scale = 1.0f / scales[sample];

    const int tl  = tid >> 2;          // trajectory within lane (0..63)
    const int sub = tid & 3;

    float acc0 = 0.0f, acc1 = 0.0f;
    if (tl < cnt) {
        const float4* base = reinterpret_cast<const float4*>(cand)
                             + (size_t)(ts_start + tl) * 25;
        const float2* gt2 = reinterpret_cast<const float2*>(gt) + sample * 50;
        #pragma unroll
        for (int j = 0; j < 7; j++) {
            const int r = sub + 4 * j;
            if (r < 25) {
                float4 v  = base[r];
                float2 g0 = __ldg(&gt2[2 * r]);
                float2 g1 = __ldg(&gt2[2 * r + 1]);
                float dx0 = v.x - g0.x, dy0 = v.y - g0.y;
                float dx1 = v.z - g1.x, dy1 = v.w - g1.y;
                acc0 += fsqrt_approx(fmaf(dx0, dx0, fmaf(dy0, dy0, 1e-12f)));
                acc1 += fsqrt_approx(fmaf(dx1, dx1, fmaf(dy1, dy1, 1e-12f)));
            }
        }
    }
    float acc = acc0 + acc1;
    acc += __shfl_xor_sync(0xffffffffu, acc, 1);
    acc += __shfl_xor_sync(0xffffffffu, acc, 2);

    if (sub == 0 && tl < cnt)
        g_score[ts_start + tl] = -(acc * 0.02f) * inv_scale;
}

// ---------------------------------------------------------------------------
// Kernel B (fused tail): one block per sample, 512 threads = 16 warps.
//   warp w: fused softmax-CE for lanes s+w (and s+w+16 if present) -> smem
//   warp 0: lane-level log-softmax + oracle-weighted average -> g_sample_loss
//   last block: deterministic fixed-order mean over B -> d_out[0]; reset ticket
// ---------------------------------------------------------------------------
__global__ __launch_bounds__(512)
void sample_fused_kernel(const float* __restrict__ traj_scores, // [NT]
                         const float* __restrict__ lane_scores, // [NL]
                         const int*   __restrict__ oracle,      // [NL]
                         const int*   __restrict__ cls_se,      // [B, 2]
                         const int*   __restrict__ trj_se,      // [NL, 2]
                         float* __restrict__ out, int B)
{
    const int b   = blockIdx.x;
    const int tid = threadIdx.x;
    const int wid = tid >> 5;
    const int lid = tid & 31;

    const int s = cls_se[2 * b];
    const int e = cls_se[2 * b + 1];
    int nlanes = e - s;
    if (nlanes > 32) nlanes = 32;

    __shared__ float s_ce[32];
    __shared__ bool  s_last;

    // each warp handles lanes wid and wid+16
    #pragma unroll
    for (int pass = 0; pass < 2; pass++) {
        const int li = wid + 16 * pass;
        if (li < nlanes) {
            const int lane = s + li;
            const int ts_start = trj_se[2 * lane];
            const int ts_end   = trj_se[2 * lane + 1];
            int cnt = ts_end - ts_start;
            if (cnt > 64) cnt = 64;

            const bool actA = (lid < cnt);
            const bool actB = (lid + 32 < cnt);
            float sA = actA ? g_score[ts_start + lid]          : -FLT_MAX;
            float sB = actB ? g_score[ts_start + lid + 32]     : -FLT_MAX;
            float tA = actA ? traj_scores[ts_start + lid]      : -FLT_MAX;
            float tB = actB ? traj_scores[ts_start + lid + 32] : -FLT_MAX;

            float ce = warp_lane_ce(actA, actB, sA, sB, tA, tB);
            if (lid == 0) s_ce[li] = ce;
        }
    }
    __syncthreads();

    // warp 0: sample-level loss over nlanes (<=32) lanes
    if (wid == 0) {
        const bool act = (lid < nlanes);
        float ls  = act ? lane_scores[s + lid] : -FLT_MAX;
        bool  orc = act && (oracle[s + lid] != 0);
        float ce  = orc ? s_ce[lid] : 0.0f;

        float m = ls;
        #pragma unroll
        for (int o = 16; o; o >>= 1)
            m = fmaxf(m, __shfl_xor_sync(0xffffffffu, m, o));

        float ev = act ? expf(ls - m) : 0.0f;
        float oc = orc ? 1.0f : 0.0f;
        float Z = ev, OC = oc, CE = ce;
        #pragma unroll
        for (int o = 16; o; o >>= 1) {
            Z  += __shfl_xor_sync(0xffffffffu, Z, o);
            OC += __shfl_xor_sync(0xffffffffu, OC, o);
            CE += __shfl_xor_sync(0xffffffffu, CE, o);
        }
        const float lse = logf(Z);
        float llc = orc ? (m + lse - ls) : 0.0f;
        float LL = llc;
        #pragma unroll
        for (int o = 16; o; o >>= 1)
            LL += __shfl_xor_sync(0xffffffffu, LL, o);

        if (lid == 0)
            g_sample_loss[b] = (LL / OC) * LANE_WEIGHT + CE / OC;
    }

    // ---- last-block-done: deterministic final mean ----
    __threadfence();
    __syncthreads();
    if (tid == 0) {
        int t = atomicAdd(&g_done, 1);
        s_last = (t == gridDim.x - 1);
    }
    __syncthreads();
    if (!s_last) return;

    __threadfence();   // make all g_sample_loss writes visible
    __shared__ float red[16];
    float v = 0.0f;
    for (int i = tid; i < B; i += 512) v += g_sample_loss[i];
    #pragma unroll
    for (int o = 16; o; o >>= 1) v += __shfl_xor_sync(0xffffffffu, v, o);
    if (lid == 0) red[wid] = v;
    __syncthreads();
    if (wid == 0) {
        float a = (lid < 16) ? red[lid] : 0.0f;
        #pragma unroll
        for (int o = 8; o; o >>= 1) a += __shfl_xor_sync(0xffffffffu, a, o);
        if (lid == 0) {
            out[0] = a / (float)B;
            *((volatile int*)&g_done) = 0;   // reset for next graph replay
        }
    }
}

// ---------------------------------------------------------------------------
// Generic fallback (any T): block-per-lane ADE + in-block epilogue.
// ---------------------------------------------------------------------------
__global__ __launch_bounds__(256)
void traj_ce_kernel(const float* __restrict__ traj_scores,
                    const float* __restrict__ cand,
                    const float* __restrict__ gt,
                    const float* __restrict__ scales,
                    const int*   __restrict__ cls_se,
                    const int*   __restrict__ trj_se,
                    int B, int T)
{
    const int lane = blockIdx.x;
    const int tid  = threadIdx.x;

    const int ts_start = trj_se[2 * lane];
    const int ts_end   = trj_se[2 * lane + 1];
    int cnt = ts_end - ts_start;
    if (cnt > 64) cnt = 64;

    const int sample = find_sample(cls_se, B, lane);

    __shared__ __align__(8) float s_gt[1024];
    __shared__ float s_score[64], s_ts[64];

    const int t2 = T * 2;
    for (int i = tid; i < t2 && i < 1024; i += blockDim.x)
        s_gt[i] = gt[(size_t)sample * t2 + i];
    __syncthreads();

    const float inv_scale = 1.0f / scales[sample];

    const int q   = tid >> 2;
    const int sub = tid & 3;
    float acc = 0.0f;
    if (q < cnt) {
        const float2* base = reinterpret_cast<const float2*>(cand)
                             + (size_t)(ts_start + q) * T;
        const float2* g2 = reinterpret_cast<const float2*>(s_gt);
        #pragma unroll 4
        for (int t = sub; t < T; t += 4) {
            float2 c = base[t];
            float2 g = g2[t];
            float dx = c.x - g.x;
            float dy = c.y - g.y;
            acc += fsqrt_approx(fmaf(dx, dx, fmaf(dy, dy, 1e-12f)));
        }
    }
    acc += __shfl_xor_sync(0xffffffffu, acc, 1);
    acc += __shfl_xor_sync(0xffffffffu, acc, 2);

    if (sub == 0 && q < cnt) {
        float ade = acc / (float)T;
        s_score[q] = -ade * inv_scale;
        s_ts[q]    = traj_scores[ts_start + q];
    }
    __syncthreads();

    if (tid >= 32) return;
    const bool actA = (tid < cnt);
    const bool actB = (tid + 32 < cnt);
    float sA = actA ? s_score[tid]      : -FLT_MAX;
    float sB = actB ? s_score[tid + 32] : -FLT_MAX;
    float tA = actA ? s_ts[tid]         : -FLT_MAX;
    float tB = actB ? s_ts[tid + 32]    : -FLT_MAX;
    float ce = warp_lane_ce(actA, actB, sA, sB, tA, tB);
    if (tid == 0) g_ce_lane[lane] = ce;
}

__global__ __launch_bounds__(32)
void sample_loss_kernel(const float* __restrict__ lane_scores,
                        const int*   __restrict__ oracle,
                        const int*   __restrict__ cls_se)
{
    const int b = blockIdx.x;
    const int i = threadIdx.x;
    const int s = cls_se[2 * b];
    const int e = cls_se[2 * b + 1];
    int cnt = e - s;
    if (cnt > 32) cnt = 32;

    const bool act = (i < cnt);
    float ls  = act ? lane_scores[s + i] : -FLT_MAX;
    bool  orc = act && (oracle[s + i] != 0);
    float ce  = orc ? g_ce_lane[s + i] : 0.0f;

    float m = ls;
    #pragma unroll
    for (int o = 16; o; o >>= 1) m = fmaxf(m, __shfl_xor_sync(0xffffffffu, m, o));

    float ev = act ? expf(ls - m) : 0.0f;
    float oc = orc ? 1.0f : 0.0f;
    float Z = ev, OC = oc, CE = ce;
    #pragma unroll
    for (int o = 16; o; o >>= 1) {
        Z  += __shfl_xor_sync(0xffffffffu, Z, o);
        OC += __shfl_xor_sync(0xffffffffu, OC, o);
        CE += __shfl_xor_sync(0xffffffffu, CE, o);
    }
    const float lse = logf(Z);
    float llc = orc ? (m + lse - ls) : 0.0f;
    float LL = llc;
    #pragma unroll
    for (int o = 16; o; o >>= 1) LL += __shfl_xor_sync(0xffffffffu, LL, o);

    if (i == 0)
        g_sample_loss[b] = (LL / OC) * LANE_WEIGHT + CE / OC;
}

__global__ __launch_bounds__(256)
void final_mean_kernel(float* __restrict__ out, int B)
{
    __shared__ float red[256];
    const int tid = threadIdx.x;
    float v = 0.0f;
    for (int i = tid; i < B; i += 256) v += g_sample_loss[i];
    red[tid] = v;
    __syncthreads();
    for (int o = 128; o >= 32; o >>= 1) {
        if (tid < o) red[tid] += red[tid + o];
        __syncthreads();
    }
    if (tid < 32) {
        float a = red[tid];
        #pragma unroll
        for (int o = 16; o; o >>= 1) a += __shfl_xor_sync(0xffffffffu, a, o);
        if (tid == 0) out[0] = a / (float)B;
    }
}

// ---------------------------------------------------------------------------
extern "C" void kernel_launch(void* const* d_in, const int* in_sizes, int n_in,
                              void* d_out, int out_size)
{
    const float* lane_scores = (const float*)d_in[0];   // [NL]
    const float* traj_scores = (const float*)d_in[1];   // [NT, 1]
    const float* cand        = (const float*)d_in[2];   // [NT, T, 2]
    const float* gt          = (const float*)d_in[3];   // [B, T, 2]
    const float* scales      = (const float*)d_in[4];   // [B]
    const int*   oracle      = (const int*)  d_in[5];   // [NL]
    const int*   cls_se      = (const int*)  d_in[6];   // [B, 2]
    const int*   trj_se      = (const int*)  d_in[7];   // [NL, 2]

    const int NL = in_sizes[0];
    const int NT = in_sizes[1];
    const int B  = in_sizes[6] / 2;
    const int T  = in_sizes[3] / (2 * B);

    if (T == 50 && NT <= 524288 && B <= 8192) {
        traj_ade_T50_kernel<<<NL, 256>>>(cand, gt, scales, cls_se, trj_se, B);
        sample_fused_kernel<<<B, 512>>>(traj_scores, lane_scores, oracle,
                                        cls_se, trj_se, (float*)d_out, B);
    } else {
        traj_ce_kernel<<<NL, 256>>>(traj_scores, cand, gt, scales,
                                    cls_se, trj_se, B, T);
        sample_loss_kernel<<<B, 32>>>(lane_scores, oracle, cls_se);
        final_mean_kernel<<<1, 256>>>((float*)d_out, B);
    }
}